// round 2
// baseline (speedup 1.0000x reference)
#include <cuda_runtime.h>

// y[b, i, c] = x[b, i+1, c] - x[b, i, c]
// x: [B=64, L=16384, C=32] fp32, y: [B, L-1, C] fp32
// C*4 = 128 bytes per row; shift of one row = 8 float4s.

static constexpr int B = 64;
static constexpr int L = 16384;
static constexpr int C = 32;
static constexpr int IN_V4_PER_B  = L * C / 4;        // 131072
static constexpr int OUT_V4_PER_B = (L - 1) * C / 4;  // 131064

__global__ void __launch_bounds__(256) diff1d_kernel(
    const float4* __restrict__ x, float4* __restrict__ y)
{
    const int b = blockIdx.y;
    const int idx = blockIdx.x * blockDim.x + threadIdx.x;
    if (idx >= OUT_V4_PER_B) return;

    const float4* __restrict__ xin = x + (size_t)b * IN_V4_PER_B;
    float4* __restrict__ yout = y + (size_t)b * OUT_V4_PER_B;

    const float4 a  = xin[idx];
    const float4 bb = xin[idx + 8];   // +32 floats = next row along L

    float4 r;
    r.x = bb.x - a.x;
    r.y = bb.y - a.y;
    r.z = bb.z - a.z;
    r.w = bb.w - a.w;

    yout[idx] = r;
}

extern "C" void kernel_launch(void* const* d_in, const int* in_sizes, int n_in,
                              void* d_out, int out_size)
{
    (void)in_sizes; (void)n_in; (void)out_size;
    const float4* x = (const float4*)d_in[0];
    float4* y = (float4*)d_out;

    dim3 block(256);
    dim3 grid((OUT_V4_PER_B + 255) / 256, B);
    diff1d_kernel<<<grid, block>>>(x, y);
}

// round 3
// speedup vs baseline: 1.0374x; 1.0374x over previous
#include <cuda_runtime.h>

// y[b, i, c] = x[b, i+1, c] - x[b, i, c]
// x: [B=64, L=16384, C=32] fp32, y: [B, L-1, C] fp32
// Row = 32 floats = 8 float4 = 128 bytes; the "+1 row" shift = +8 vec4s.

static constexpr int B = 64;
static constexpr int L = 16384;
static constexpr int C = 32;
static constexpr int IN_V4_PER_B  = L * C / 4;        // 131072
static constexpr int OUT_V4_PER_B = (L - 1) * C / 4;  // 131064
static constexpr int VPT = 4;                         // vec4s per thread
static constexpr int TPB = 256;
static constexpr int V4_PER_BLOCK = VPT * TPB;        // 1024

__global__ void __launch_bounds__(TPB) diff1d_kernel(
    const float4* __restrict__ x, float4* __restrict__ y)
{
    const int b = blockIdx.y;
    const float4* __restrict__ xin = x + (size_t)b * IN_V4_PER_B;
    float4* __restrict__ yout = y + (size_t)b * OUT_V4_PER_B;

    const int base = blockIdx.x * V4_PER_BLOCK + threadIdx.x;

    if (blockIdx.x != gridDim.x - 1) {
        // Full block: branch-free, all 8 loads front-batched for max MLP.
        float4 a[VPT], bb[VPT];
#pragma unroll
        for (int k = 0; k < VPT; k++) {
            const int i = base + k * TPB;
            a[k]  = xin[i];
            bb[k] = xin[i + 8];
        }
#pragma unroll
        for (int k = 0; k < VPT; k++) {
            const int i = base + k * TPB;
            float4 r;
            r.x = bb[k].x - a[k].x;
            r.y = bb[k].y - a[k].y;
            r.z = bb[k].z - a[k].z;
            r.w = bb[k].w - a[k].w;
            yout[i] = r;
        }
    } else {
        // Tail block: guarded.
#pragma unroll
        for (int k = 0; k < VPT; k++) {
            const int i = base + k * TPB;
            if (i < OUT_V4_PER_B) {
                const float4 a  = xin[i];
                const float4 bb = xin[i + 8];
                float4 r;
                r.x = bb.x - a.x;
                r.y = bb.y - a.y;
                r.z = bb.z - a.z;
                r.w = bb.w - a.w;
                yout[i] = r;
            }
        }
    }
}

extern "C" void kernel_launch(void* const* d_in, const int* in_sizes, int n_in,
                              void* d_out, int out_size)
{
    (void)in_sizes; (void)n_in; (void)out_size;
    const float4* x = (const float4*)d_in[0];
    float4* y = (float4*)d_out;

    dim3 block(TPB);
    dim3 grid((OUT_V4_PER_B + V4_PER_BLOCK - 1) / V4_PER_BLOCK, B);  // (128, 64)
    diff1d_kernel<<<grid, block>>>(x, y);
}

// round 4
// speedup vs baseline: 1.0381x; 1.0007x over previous
#include <cuda_runtime.h>
#include <cstdint>

// y[b, i, c] = x[b, i+1, c] - x[b, i, c]
// x: [B=64, L=16384, C=32] fp32, y: [B, L-1, C] fp32
// Row = 32 floats = 128 bytes = 4 v8-chunks (v8 = 8 fp32 = 32 B, Blackwell 256-bit ld/st).
// The "+1 row" shift = +4 v8 units.

static constexpr int B = 64;
static constexpr int L = 16384;
static constexpr int C = 32;
static constexpr int IN_V8_PER_B  = L * C / 8;        // 65536
static constexpr int OUT_V8_PER_B = (L - 1) * C / 8;  // 65532
static constexpr int VPT = 4;                         // v8 chunks per thread
static constexpr int TPB = 256;
static constexpr int V8_PER_BLOCK = VPT * TPB;        // 1024

struct V8 { float v[8]; };

__device__ __forceinline__ void ldg_v8(const float* p, V8& r) {
    asm volatile(
        "ld.global.v8.b32 {%0,%1,%2,%3,%4,%5,%6,%7}, [%8];"
        : "=f"(r.v[0]), "=f"(r.v[1]), "=f"(r.v[2]), "=f"(r.v[3]),
          "=f"(r.v[4]), "=f"(r.v[5]), "=f"(r.v[6]), "=f"(r.v[7])
        : "l"(p));
}

__device__ __forceinline__ void stg_cs_v8(float* p, const V8& r) {
    asm volatile(
        "st.global.cs.v8.b32 [%0], {%1,%2,%3,%4,%5,%6,%7,%8};"
        :: "l"(p),
           "f"(r.v[0]), "f"(r.v[1]), "f"(r.v[2]), "f"(r.v[3]),
           "f"(r.v[4]), "f"(r.v[5]), "f"(r.v[6]), "f"(r.v[7])
        : "memory");
}

__global__ void __launch_bounds__(TPB) diff1d_kernel(
    const float* __restrict__ x, float* __restrict__ y)
{
    const int b = blockIdx.y;
    const float* __restrict__ xin = x + (size_t)b * (IN_V8_PER_B * 8);
    float* __restrict__ yout = y + (size_t)b * (OUT_V8_PER_B * 8);

    const int base = blockIdx.x * V8_PER_BLOCK + threadIdx.x;  // in v8 units

    if (blockIdx.x != gridDim.x - 1) {
        // Full block: branch-free, all 8 loads front-batched.
        V8 a[VPT], bb[VPT];
#pragma unroll
        for (int k = 0; k < VPT; k++) {
            const int i = base + k * TPB;
            ldg_v8(xin + (size_t)i * 8, a[k]);
            ldg_v8(xin + (size_t)(i + 4) * 8, bb[k]);
        }
#pragma unroll
        for (int k = 0; k < VPT; k++) {
            const int i = base + k * TPB;
            V8 r;
#pragma unroll
            for (int j = 0; j < 8; j++) r.v[j] = bb[k].v[j] - a[k].v[j];
            stg_cs_v8(yout + (size_t)i * 8, r);
        }
    } else {
        // Tail block: guarded per chunk.
#pragma unroll
        for (int k = 0; k < VPT; k++) {
            const int i = base + k * TPB;
            if (i < OUT_V8_PER_B) {
                V8 a, bb, r;
                ldg_v8(xin + (size_t)i * 8, a);
                ldg_v8(xin + (size_t)(i + 4) * 8, bb);
#pragma unroll
                for (int j = 0; j < 8; j++) r.v[j] = bb.v[j] - a.v[j];
                stg_cs_v8(yout + (size_t)i * 8, r);
            }
        }
    }
}

extern "C" void kernel_launch(void* const* d_in, const int* in_sizes, int n_in,
                              void* d_out, int out_size)
{
    (void)in_sizes; (void)n_in; (void)out_size;
    const float* x = (const float*)d_in[0];
    float* y = (float*)d_out;

    dim3 block(TPB);
    dim3 grid((OUT_V8_PER_B + V8_PER_BLOCK - 1) / V8_PER_BLOCK, B);  // (64, 64)
    diff1d_kernel<<<grid, block>>>(x, y);
}